// round 1
// baseline (speedup 1.0000x reference)
#include <cuda_runtime.h>
#include <math.h>

// Problem constants
#define BS   1024
#define CH   3
#define IMG  64
#define KPATCH 16
#define NC   10
#define HID  1024
#define LAT  128
#define OH   4            // IMG / KPATCH
#define LPATCH 16         // OH*OH
#define PD   768          // CH*K*K
#define MROWS (BS * LPATCH)   // 16384

// Padded strides (multiples of 16 floats for alignment)
#define LDA1 784          // 768 + 10 c + pad -> 784
#define KB1  778
#define LDA3 144          // 128 mu + 10 c + pad -> 144
#define KB3  138

// Output layout: recon (BS*CH*IMG*IMG) then mu_logvar_2d (BS*2LAT*OH*OH)
#define RECON_ELEMS (BS * CH * IMG * IMG)        // 12582912
#define ML_OFFSET   RECON_ELEMS

// ---------------- scratch (device globals; no runtime allocation) ----------
__device__ float g_A1[(size_t)MROWS * LDA1];   // encoder input  [16384 x 784]
__device__ float g_H [(size_t)MROWS * HID];    // encoder hidden [16384 x 1024]
__device__ float g_A3[(size_t)MROWS * LDA3];   // decoder input  [16384 x 144]
__device__ float g_HD[(size_t)MROWS * HID];    // decoder hidden [16384 x 1024]

// ---------------- patchify: x,c -> A1 --------------------------------------
// A1[row][j]: row = b*16 + l, l = oh*4+ow
//   j <  768 : x[b][j>>8][oh*16 + ((j>>4)&15)][ow*16 + (j&15)]
//   768..777 : c[b][j-768]
//   778..783 : 0
__global__ void patchify_kernel(const float* __restrict__ x,
                                const float* __restrict__ c,
                                float* __restrict__ A1) {
    int row = blockIdx.x;                    // 0..16383
    int b = row >> 4;
    int l = row & 15;
    int oh = l >> 2, ow = l & 3;
    const float* xb = x + (size_t)b * (CH * IMG * IMG);
    float* arow = A1 + (size_t)row * LDA1;

    for (int j4 = threadIdx.x; j4 < LDA1 / 4; j4 += blockDim.x) {
        int j = j4 * 4;
        float4 v;
        if (j < PD) {
            int ch = j >> 8;
            int kh = (j >> 4) & 15;
            int kw = j & 15;                 // multiple of 4
            const float* src = xb + ch * (IMG * IMG) + (oh * KPATCH + kh) * IMG
                             + ow * KPATCH + kw;
            v = *(const float4*)src;
        } else {
            float t[4];
#pragma unroll
            for (int q = 0; q < 4; q++) {
                int jj = j + q;
                t[q] = (jj < PD + NC) ? c[b * NC + (jj - PD)] : 0.0f;
            }
            v = make_float4(t[0], t[1], t[2], t[3]);
        }
        *(float4*)(arow + j) = v;
    }
}

// ---------------- A3 tail: cols 128..143 = [c | zeros] ---------------------
__global__ void a3_tail_kernel(const float* __restrict__ c,
                               float* __restrict__ A3) {
    int idx = blockIdx.x * blockDim.x + threadIdx.x;   // 16384*16
    if (idx >= MROWS * 16) return;
    int row = idx >> 4;
    int col = LAT + (idx & 15);                        // 128..143
    float v = 0.0f;
    if (col < LAT + NC) v = c[(row >> 4) * NC + (col - LAT)];
    A3[(size_t)row * LDA3 + col] = v;
}

// ---------------- tiled fp32 GEMM with fused epilogues ----------------------
// C(MxN) = A(M x lda, logical K<=Kloop) * B(KB x N) + bias, epilogue EPI.
// BM=BN=128, BK=16, 256 threads, 8x8 per thread.
// EPI 0: ReLU -> C row-major (ldc = N)
// EPI 1: mu_logvar: write transposed to C (out2: [b][f][l]) and mu cols (<128)
//        into C2 (A3, stride LDA3)
// EPI 2: sigmoid + depatchify scatter into recon (C = d_out base)
#define BM 128
#define BN 128
#define BKT 16

template <int EPI>
__global__ __launch_bounds__(256)
void gemm_kernel(const float* __restrict__ A, int lda,
                 const float* __restrict__ B,
                 const float* __restrict__ bias,
                 float* __restrict__ C,
                 float* __restrict__ C2,
                 int N, int Kloop, int KB) {
    __shared__ float As[BKT][BM + 4];
    __shared__ float Bs[BKT][BN];

    const int tid = threadIdx.x;
    const int tx = tid & 15;        // N direction
    const int ty = tid >> 4;        // M direction
    const int n0 = blockIdx.x * BN;
    const int m0 = blockIdx.y * BM;

    float acc[8][8];
#pragma unroll
    for (int i = 0; i < 8; i++)
#pragma unroll
        for (int j = 0; j < 8; j++) acc[i][j] = 0.0f;

    for (int kb = 0; kb < Kloop; kb += BKT) {
        // Load A tile (BM x BKT), transpose into As[k][m]
#pragma unroll
        for (int it = 0; it < 2; it++) {
            int f = it * 256 + tid;            // 0..511
            int r = f >> 2;                    // 0..127
            int k4 = (f & 3) * 4;
            float4 v = *(const float4*)(A + (size_t)(m0 + r) * lda + kb + k4);
            As[k4 + 0][r] = v.x;
            As[k4 + 1][r] = v.y;
            As[k4 + 2][r] = v.z;
            As[k4 + 3][r] = v.w;
        }
        // Load B tile (BKT x BN), guarded at true KB
#pragma unroll
        for (int it = 0; it < 2; it++) {
            int f = it * 256 + tid;
            int kr = f >> 5;                   // 0..15
            int n4 = (f & 31) * 4;
            float4 v;
            if (kb + kr < KB)
                v = *(const float4*)(B + (size_t)(kb + kr) * N + n0 + n4);
            else
                v = make_float4(0.f, 0.f, 0.f, 0.f);
            *(float4*)&Bs[kr][n4] = v;
        }
        __syncthreads();

#pragma unroll
        for (int k = 0; k < BKT; k++) {
            float a[8], bz[8];
            *(float4*)&a[0]  = *(const float4*)&As[k][ty * 8];
            *(float4*)&a[4]  = *(const float4*)&As[k][ty * 8 + 4];
            *(float4*)&bz[0] = *(const float4*)&Bs[k][tx * 8];
            *(float4*)&bz[4] = *(const float4*)&Bs[k][tx * 8 + 4];
#pragma unroll
            for (int i = 0; i < 8; i++)
#pragma unroll
                for (int j = 0; j < 8; j++)
                    acc[i][j] = fmaf(a[i], bz[j], acc[i][j]);
        }
        __syncthreads();
    }

    const int mbase = m0 + ty * 8;
    const int nbase = n0 + tx * 8;

    float bv[8];
    *(float4*)&bv[0] = *(const float4*)(bias + nbase);
    *(float4*)&bv[4] = *(const float4*)(bias + nbase + 4);

    if (EPI == 0) {
        // ReLU -> row-major C
#pragma unroll
        for (int i = 0; i < 8; i++) {
            float4 v0, v1;
            v0.x = fmaxf(acc[i][0] + bv[0], 0.f);
            v0.y = fmaxf(acc[i][1] + bv[1], 0.f);
            v0.z = fmaxf(acc[i][2] + bv[2], 0.f);
            v0.w = fmaxf(acc[i][3] + bv[3], 0.f);
            v1.x = fmaxf(acc[i][4] + bv[4], 0.f);
            v1.y = fmaxf(acc[i][5] + bv[5], 0.f);
            v1.z = fmaxf(acc[i][6] + bv[6], 0.f);
            v1.w = fmaxf(acc[i][7] + bv[7], 0.f);
            float* cp = C + (size_t)(mbase + i) * N + nbase;
            *(float4*)cp = v0;
            *(float4*)(cp + 4) = v1;
        }
    } else if (EPI == 1) {
        // mu_logvar: out2[b][f][l] = val; mu (f<128) -> C2[row*LDA3 + f]
#pragma unroll
        for (int i = 0; i < 8; i++) {
            int row = mbase + i;
            int b = row >> 4, l = row & 15;
            float vals[8];
#pragma unroll
            for (int j = 0; j < 8; j++) vals[j] = acc[i][j] + bv[j];
            float* outp = C + (size_t)b * (2 * LAT * LPATCH) + l;
#pragma unroll
            for (int j = 0; j < 8; j++)
                outp[(size_t)(nbase + j) * LPATCH] = vals[j];
            if (nbase < LAT) {
                float* mp = C2 + (size_t)row * LDA3 + nbase;
                *(float4*)mp       = make_float4(vals[0], vals[1], vals[2], vals[3]);
                *(float4*)(mp + 4) = make_float4(vals[4], vals[5], vals[6], vals[7]);
            }
        }
    } else {
        // sigmoid + depatchify scatter into recon
        int ch  = nbase >> 8;
        int kh  = (nbase >> 4) & 15;
        int kw0 = nbase & 15;          // 0 or 8
#pragma unroll
        for (int i = 0; i < 8; i++) {
            int row = mbase + i;
            int b = row >> 4, l = row & 15;
            int oh = l >> 2, ow = l & 3;
            float* op = C + (size_t)b * (CH * IMG * IMG) + ch * (IMG * IMG)
                      + (oh * KPATCH + kh) * IMG + ow * KPATCH + kw0;
            float4 v0, v1;
            v0.x = 1.0f / (1.0f + expf(-(acc[i][0] + bv[0])));
            v0.y = 1.0f / (1.0f + expf(-(acc[i][1] + bv[1])));
            v0.z = 1.0f / (1.0f + expf(-(acc[i][2] + bv[2])));
            v0.w = 1.0f / (1.0f + expf(-(acc[i][3] + bv[3])));
            v1.x = 1.0f / (1.0f + expf(-(acc[i][4] + bv[4])));
            v1.y = 1.0f / (1.0f + expf(-(acc[i][5] + bv[5])));
            v1.z = 1.0f / (1.0f + expf(-(acc[i][6] + bv[6])));
            v1.w = 1.0f / (1.0f + expf(-(acc[i][7] + bv[7])));
            *(float4*)op = v0;
            *(float4*)(op + 4) = v1;
        }
    }
}

// ---------------- launch ----------------------------------------------------
extern "C" void kernel_launch(void* const* d_in, const int* in_sizes, int n_in,
                              void* d_out, int out_size) {
    const float* x      = (const float*)d_in[0];
    const float* c      = (const float*)d_in[1];
    const float* enc_w1 = (const float*)d_in[2];
    const float* enc_b1 = (const float*)d_in[3];
    const float* enc_w2 = (const float*)d_in[4];
    const float* enc_b2 = (const float*)d_in[5];
    const float* dec_w1 = (const float*)d_in[6];
    const float* dec_b1 = (const float*)d_in[7];
    const float* dec_w2 = (const float*)d_in[8];
    const float* dec_b2 = (const float*)d_in[9];
    float* out = (float*)d_out;

    float *A1, *H, *A3, *HD;
    cudaGetSymbolAddress((void**)&A1, g_A1);
    cudaGetSymbolAddress((void**)&H,  g_H);
    cudaGetSymbolAddress((void**)&A3, g_A3);
    cudaGetSymbolAddress((void**)&HD, g_HD);

    // Stage 0: build inputs
    patchify_kernel<<<MROWS, 128>>>(x, c, A1);
    a3_tail_kernel<<<(MROWS * 16 + 255) / 256, 256>>>(c, A3);

    dim3 blk(256);

    // GEMM1: A1(784) x enc_w1(778x1024) -> H, ReLU
    gemm_kernel<0><<<dim3(HID / BN, MROWS / BM), blk>>>(
        A1, LDA1, enc_w1, enc_b1, H, nullptr, HID, LDA1, KB1);

    // GEMM2: H(1024) x enc_w2(1024x256) -> mu_logvar_2d + mu into A3
    gemm_kernel<1><<<dim3(2 * LAT / BN, MROWS / BM), blk>>>(
        H, HID, enc_w2, enc_b2, out + ML_OFFSET, A3, 2 * LAT, HID, HID);

    // GEMM3: A3(144) x dec_w1(138x1024) -> HD, ReLU
    gemm_kernel<0><<<dim3(HID / BN, MROWS / BM), blk>>>(
        A3, LDA3, dec_w1, dec_b1, HD, nullptr, HID, LDA3, KB3);

    // GEMM4: HD(1024) x dec_w2(1024x768) -> sigmoid -> recon scatter
    gemm_kernel<2><<<dim3(PD / BN, MROWS / BM), blk>>>(
        HD, HID, dec_w2, dec_b2, out, nullptr, PD, HID, HID);
}

// round 3
// speedup vs baseline: 3.5334x; 3.5334x over previous
#include <cuda_runtime.h>
#include <cstdint>
#include <math.h>

// ---------------- problem constants ----------------
#define BS     1024
#define CHN    3
#define IMG    64
#define KP     16
#define NC     10
#define HID    1024
#define LAT    128
#define LP     16
#define PD     768
#define MROWS  (BS * LP)        // 16384

#define KPAD1  800              // 778 -> 800
#define KB1    778
#define KPAD3  160              // 138 -> 160
#define KB3    138

#define RECON_ELEMS (BS * CHN * IMG * IMG)
#define ML_OFFSET   RECON_ELEMS

// GEMM tile config
#define TMT 128
#define TNT 128
#define TKT 32

// SMEM (floats): As[128][36], Bs[32][136], double-buffered
#define APAD 36
#define BPAD 136
#define SA_BYTES (TMT * APAD * 4)        // 18432
#define SB_BYTES (TKT * BPAD * 4)        // 17408
#define SA0 0
#define SA1 SA_BYTES
#define SB0 (2 * SA_BYTES)
#define SB1 (2 * SA_BYTES + SB_BYTES)
#define SMEM_BYTES (2 * SA_BYTES + 2 * SB_BYTES)   // 71680

// ---------------- scratch ----------------
__device__ float g_A1[(size_t)MROWS * KPAD1];
__device__ float g_H [(size_t)MROWS * HID];
__device__ float g_A3[(size_t)MROWS * KPAD3];
__device__ float g_HD[(size_t)MROWS * HID];
__device__ float g_W1[(size_t)KPAD1 * HID];        // tf32 enc_w1, padded
__device__ float g_W2[(size_t)HID * (2 * LAT)];    // tf32 enc_w2
__device__ float g_W3[(size_t)KPAD3 * HID];        // tf32 dec_w1, padded
__device__ float g_W4[(size_t)HID * PD];           // tf32 dec_w2

// ---------------- helpers ----------------
__device__ __forceinline__ uint32_t smem_u32(const void* p) {
    uint32_t a;
    asm("{ .reg .u64 t; cvta.to.shared.u64 t, %1; cvt.u32.u64 %0, t; }"
        : "=r"(a) : "l"(p));
    return a;
}
__device__ __forceinline__ float to_tf32(float x) {
    uint32_t u;
    asm("cvt.rna.tf32.f32 %0, %1;" : "=r"(u) : "f"(x));
    return __uint_as_float(u);
}
#define CP16(dst, src) \
    asm volatile("cp.async.cg.shared.global [%0], [%1], 16;" :: "r"(dst), "l"(src) : "memory")
#define CP_COMMIT() asm volatile("cp.async.commit_group;" ::: "memory")
#define CP_WAIT(n)  asm volatile("cp.async.wait_group %0;" :: "n"(n) : "memory")

__device__ __forceinline__ void mma_tf32(float c[4],
                                         uint32_t a0, uint32_t a1, uint32_t a2, uint32_t a3,
                                         uint32_t b0, uint32_t b1) {
    asm volatile(
        "mma.sync.aligned.m16n8k8.row.col.f32.tf32.tf32.f32 "
        "{%0,%1,%2,%3}, {%4,%5,%6,%7}, {%8,%9}, {%0,%1,%2,%3};"
        : "+f"(c[0]), "+f"(c[1]), "+f"(c[2]), "+f"(c[3])
        : "r"(a0), "r"(a1), "r"(a2), "r"(a3), "r"(b0), "r"(b1));
}

// ---------------- prep kernels ----------------
__global__ void patchify_kernel(const float* __restrict__ x,
                                const float* __restrict__ c,
                                float* __restrict__ A1) {
    int row = blockIdx.x;
    int b = row >> 4, l = row & 15;
    int oh = l >> 2, ow = l & 3;
    const float* xb = x + (size_t)b * (CHN * IMG * IMG);
    float* arow = A1 + (size_t)row * KPAD1;
    for (int j4 = threadIdx.x; j4 < KPAD1 / 4; j4 += blockDim.x) {
        int j = j4 * 4;
        float4 v;
        if (j < PD) {
            int ch = j >> 8, kh = (j >> 4) & 15, kw = j & 15;
            v = *(const float4*)(xb + ch * (IMG * IMG) + (oh * KP + kh) * IMG + ow * KP + kw);
        } else {
            float t[4];
#pragma unroll
            for (int q = 0; q < 4; q++) {
                int jj = j + q;
                t[q] = (jj < PD + NC) ? c[b * NC + (jj - PD)] : 0.0f;
            }
            v = make_float4(t[0], t[1], t[2], t[3]);
        }
        v.x = to_tf32(v.x); v.y = to_tf32(v.y);
        v.z = to_tf32(v.z); v.w = to_tf32(v.w);
        *(float4*)(arow + j) = v;
    }
}

__global__ void a3_tail_kernel(const float* __restrict__ c, float* __restrict__ A3) {
    int idx = blockIdx.x * blockDim.x + threadIdx.x;   // MROWS * 32
    if (idx >= MROWS * 32) return;
    int row = idx >> 5;
    int col = LAT + (idx & 31);                        // 128..159
    float v = (col < LAT + NC) ? to_tf32(c[(row >> 4) * NC + (col - LAT)]) : 0.0f;
    A3[(size_t)row * KPAD3 + col] = v;
}

// tf32-convert W[K][N] into out[Kpad][N], zero rows >= K
__global__ void cvt_weights(const float* __restrict__ W, float* __restrict__ out,
                            int K, int N, int Kpad) {
    int idx = blockIdx.x * blockDim.x + threadIdx.x;
    int total = Kpad * N;
    if (idx >= total) return;
    int k = idx / N;
    out[idx] = (k < K) ? to_tf32(W[idx]) : 0.0f;
}

// ---------------- tf32 mma.sync GEMM ----------------
// C(M x Ntot) = A(M x kpad) * B(kpad x Ntot) + bias, fused epilogue.
// EPI 0: ReLU -> C row-major (tf32-rounded; it feeds the next GEMM)
// EPI 1: mu_logvar scatter into C ([b][f][l], exact fp32) + mu (f<128) -> C2 (tf32)
// EPI 2: sigmoid + depatchify scatter into recon (C, exact fp32)
template <int EPI>
__global__ __launch_bounds__(256, 2)
void gemm_mma(const float* __restrict__ A, int kpad,
              const float* __restrict__ B,
              const float* __restrict__ bias,
              float* __restrict__ C, float* __restrict__ C2,
              int N, int ldc, int nchunks) {
    extern __shared__ char smem[];
    const uint32_t sb = smem_u32(smem);
    float* smf = (float*)smem;

    const int tid  = threadIdx.x;
    const int wid  = tid >> 5;
    const int lane = tid & 31;
    const int wm   = wid & 1;          // 0..1 (M dir, 64 rows each)
    const int wn   = wid >> 1;         // 0..3 (N dir, 32 cols each)
    const int m0   = blockIdx.y * TMT;
    const int n0   = blockIdx.x * TNT;

    const float* Ab = A + (size_t)m0 * kpad;
    const float* Bb = B + n0;

    float acc[4][4][4];
#pragma unroll
    for (int i = 0; i < 4; i++)
#pragma unroll
        for (int j = 0; j < 4; j++)
#pragma unroll
            for (int q = 0; q < 4; q++) acc[i][j][q] = 0.0f;

    auto load_tiles = [&](int buf, int kb) {
        uint32_t adst = sb + (buf ? SA1 : SA0);
        uint32_t bdst = sb + (buf ? SB1 : SB0);
#pragma unroll
        for (int o = 0; o < 4; o++) {           // A: 128x32 floats
            int e = o * 256 + tid;              // 0..1023
            int r = e >> 3, cc = e & 7;
            CP16(adst + r * (APAD * 4) + cc * 16,
                 Ab + (size_t)r * kpad + kb + cc * 4);
        }
#pragma unroll
        for (int o = 0; o < 4; o++) {           // B: 32x128 floats
            int e = o * 256 + tid;              // 0..1023
            int k = e >> 5, c4 = e & 31;
            CP16(bdst + k * (BPAD * 4) + c4 * 16,
                 Bb + (size_t)(kb + k) * N + c4 * 4);
        }
    };

    load_tiles(0, 0);
    CP_COMMIT();

    const int lg = lane >> 2;      // 0..7
    const int li = lane & 3;       // 0..3

    for (int it = 0; it < nchunks; ++it) {
        int buf = it & 1;
        if (it + 1 < nchunks) {
            load_tiles(buf ^ 1, (it + 1) * TKT);
            CP_COMMIT();
            CP_WAIT(1);
        } else {
            CP_WAIT(0);
        }
        __syncthreads();

        const uint32_t* As = (const uint32_t*)(smf + (buf ? SA1 : SA0) / 4);
        const uint32_t* Bs = (const uint32_t*)(smf + (buf ? SB1 : SB0) / 4);

#pragma unroll
        for (int ks = 0; ks < 4; ks++) {
            uint32_t af[4][4], bf[4][2];
#pragma unroll
            for (int mt = 0; mt < 4; mt++) {
                int m = wm * 64 + mt * 16 + lg;
                int k = ks * 8 + li;
                af[mt][0] = As[m * APAD + k];
                af[mt][1] = As[(m + 8) * APAD + k];
                af[mt][2] = As[m * APAD + k + 4];
                af[mt][3] = As[(m + 8) * APAD + k + 4];
            }
#pragma unroll
            for (int nt = 0; nt < 4; nt++) {
                int n = wn * 32 + nt * 8 + lg;
                int k = ks * 8 + li;
                bf[nt][0] = Bs[k * BPAD + n];
                bf[nt][1] = Bs[(k + 4) * BPAD + n];
            }
#pragma unroll
            for (int mt = 0; mt < 4; mt++)
#pragma unroll
                for (int nt = 0; nt < 4; nt++)
                    mma_tf32(acc[mt][nt], af[mt][0], af[mt][1], af[mt][2], af[mt][3],
                             bf[nt][0], bf[nt][1]);
        }
        __syncthreads();
    }

    // ---------------- epilogue ----------------
#pragma unroll
    for (int mt = 0; mt < 4; mt++) {
        int r = m0 + wm * 64 + mt * 16 + lg;     // and r+8
#pragma unroll
        for (int nt = 0; nt < 4; nt++) {
            int cc = n0 + wn * 32 + nt * 8 + li * 2;
            float b0 = bias[cc], b1 = bias[cc + 1];
            float v0 = acc[mt][nt][0] + b0;
            float v1 = acc[mt][nt][1] + b1;
            float v2 = acc[mt][nt][2] + b0;
            float v3 = acc[mt][nt][3] + b1;

            if (EPI == 0) {
                v0 = to_tf32(fmaxf(v0, 0.f)); v1 = to_tf32(fmaxf(v1, 0.f));
                v2 = to_tf32(fmaxf(v2, 0.f)); v3 = to_tf32(fmaxf(v3, 0.f));
                *(float2*)(C + (size_t)r * ldc + cc)       = make_float2(v0, v1);
                *(float2*)(C + (size_t)(r + 8) * ldc + cc) = make_float2(v2, v3);
            } else if (EPI == 1) {
                // mu_logvar_2d: C[b][f][l]
                {
                    int b = r >> 4, l = r & 15;
                    float* op = C + (size_t)b * (2 * LAT * LP) + l;
                    op[(size_t)cc * LP]       = v0;
                    op[(size_t)(cc + 1) * LP] = v1;
                }
                {
                    int b = (r + 8) >> 4, l = (r + 8) & 15;
                    float* op = C + (size_t)b * (2 * LAT * LP) + l;
                    op[(size_t)cc * LP]       = v2;
                    op[(size_t)(cc + 1) * LP] = v3;
                }
                if (cc < LAT) {
                    *(float2*)(C2 + (size_t)r * KPAD3 + cc) =
                        make_float2(to_tf32(v0), to_tf32(v1));
                    *(float2*)(C2 + (size_t)(r + 8) * KPAD3 + cc) =
                        make_float2(to_tf32(v2), to_tf32(v3));
                }
            } else {
                v0 = 1.0f / (1.0f + __expf(-v0));
                v1 = 1.0f / (1.0f + __expf(-v1));
                v2 = 1.0f / (1.0f + __expf(-v2));
                v3 = 1.0f / (1.0f + __expf(-v3));
                int ch = cc >> 8, kh = (cc >> 4) & 15, kw = cc & 15;
                {
                    int b = r >> 4, l = r & 15;
                    int oh = l >> 2, ow = l & 3;
                    float* op = C + (size_t)b * (CHN * IMG * IMG) + ch * (IMG * IMG)
                              + (oh * KP + kh) * IMG + ow * KP + kw;
                    *(float2*)op = make_float2(v0, v1);
                }
                {
                    int rr = r + 8;
                    int b = rr >> 4, l = rr & 15;
                    int oh = l >> 2, ow = l & 3;
                    float* op = C + (size_t)b * (CHN * IMG * IMG) + ch * (IMG * IMG)
                              + (oh * KP + kh) * IMG + ow * KP + kw;
                    *(float2*)op = make_float2(v2, v3);
                }
            }
        }
    }
}

// ---------------- launch ----------------
extern "C" void kernel_launch(void* const* d_in, const int* in_sizes, int n_in,
                              void* d_out, int out_size) {
    const float* x      = (const float*)d_in[0];
    const float* c      = (const float*)d_in[1];
    const float* enc_w1 = (const float*)d_in[2];
    const float* enc_b1 = (const float*)d_in[3];
    const float* enc_w2 = (const float*)d_in[4];
    const float* enc_b2 = (const float*)d_in[5];
    const float* dec_w1 = (const float*)d_in[6];
    const float* dec_b1 = (const float*)d_in[7];
    const float* dec_w2 = (const float*)d_in[8];
    const float* dec_b2 = (const float*)d_in[9];
    float* out = (float*)d_out;

    float *A1, *H, *A3, *HD, *W1, *W2, *W3, *W4;
    cudaGetSymbolAddress((void**)&A1, g_A1);
    cudaGetSymbolAddress((void**)&H,  g_H);
    cudaGetSymbolAddress((void**)&A3, g_A3);
    cudaGetSymbolAddress((void**)&HD, g_HD);
    cudaGetSymbolAddress((void**)&W1, g_W1);
    cudaGetSymbolAddress((void**)&W2, g_W2);
    cudaGetSymbolAddress((void**)&W3, g_W3);
    cudaGetSymbolAddress((void**)&W4, g_W4);

    cudaFuncSetAttribute(gemm_mma<0>, cudaFuncAttributeMaxDynamicSharedMemorySize, SMEM_BYTES);
    cudaFuncSetAttribute(gemm_mma<1>, cudaFuncAttributeMaxDynamicSharedMemorySize, SMEM_BYTES);
    cudaFuncSetAttribute(gemm_mma<2>, cudaFuncAttributeMaxDynamicSharedMemorySize, SMEM_BYTES);

    // prep
    patchify_kernel<<<MROWS, 128>>>(x, c, A1);
    a3_tail_kernel<<<(MROWS * 32 + 255) / 256, 256>>>(c, A3);
    cvt_weights<<<(KPAD1 * HID + 255) / 256, 256>>>(enc_w1, W1, KB1, HID, KPAD1);
    cvt_weights<<<(HID * 2 * LAT + 255) / 256, 256>>>(enc_w2, W2, HID, 2 * LAT, HID);
    cvt_weights<<<(KPAD3 * HID + 255) / 256, 256>>>(dec_w1, W3, KB3, HID, KPAD3);
    cvt_weights<<<(HID * PD + 255) / 256, 256>>>(dec_w2, W4, HID, PD, HID);

    dim3 blk(256);
    // GEMM1: A1[16384 x 800] * W1[800 x 1024] -> H (ReLU, tf32)
    gemm_mma<0><<<dim3(HID / TNT, MROWS / TMT), blk, SMEM_BYTES>>>(
        A1, KPAD1, W1, enc_b1, H, nullptr, HID, HID, KPAD1 / TKT);
    // GEMM2: H * W2[1024 x 256] -> mu_logvar scatter + mu -> A3
    gemm_mma<1><<<dim3((2 * LAT) / TNT, MROWS / TMT), blk, SMEM_BYTES>>>(
        H, HID, W2, enc_b2, out + ML_OFFSET, A3, 2 * LAT, 0, HID / TKT);
    // GEMM3: A3[16384 x 160] * W3[160 x 1024] -> HD (ReLU, tf32)
    gemm_mma<0><<<dim3(HID / TNT, MROWS / TMT), blk, SMEM_BYTES>>>(
        A3, KPAD3, W3, dec_b1, HD, nullptr, HID, HID, KPAD3 / TKT);
    // GEMM4: HD * W4[1024 x 768] -> sigmoid + depatchify
    gemm_mma<2><<<dim3(PD / TNT, MROWS / TMT), blk, SMEM_BYTES>>>(
        HD, HID, W4, dec_b2, out, nullptr, PD, 0, HID / TKT);
}